// round 15
// baseline (speedup 1.0000x reference)
#include <cuda_runtime.h>
#include <cuda_fp16.h>
#include <cstdint>
#include <mma.h>
#include <math.h>

using namespace nvcuda;

// ---------------- constants ----------------
#define SEQ      2048
#define DMODEL   2048
#define HEADS    16
#define HDIM     128
#define INNER    8192
#define LN_EPS   1e-5f
#define F2H_XBLKS 8          // extra attention-grid x-slots doing weight f2h

// ---------------- scratch (static device memory; no allocations) ----------
__device__ __half g_c[SEQ * 3 * DMODEL];     // QKV (half)
__device__ __half g_attn[SEQ * DMODEL];      // attention out (half)
__device__ float  g_h1[SEQ * DMODEL];        // LN1 out fp32 (residual)
__device__ __half g_h1h[SEQ * DMODEL];       // LN1 out half (GEMM A)
__device__ __half g_ff[SEQ * INNER];         // gelu(...) half
__device__ float  g_part[2 * SEQ * DMODEL];  // split-K partial sums (fp32)
__device__ __half g_xh[SEQ * DMODEL];        // x half
__device__ __half g_Cwh[DMODEL * 3 * DMODEL];
__device__ __half g_linh[DMODEL * DMODEL];
__device__ __half g_ff1h[DMODEL * INNER];
__device__ __half g_ff2h[INNER * DMODEL];

// ---------------- helpers ----------------
__device__ __forceinline__ float gelu_f(float v) {
    return 0.5f * v * (1.0f + erff(v * 0.7071067811865476f));
}
__device__ __forceinline__ uint32_t smem_u32(const void* p) {
    uint32_t a;
    asm("{ .reg .u64 t; cvta.to.shared.u64 t, %1; cvt.u32.u64 %0, t; }"
        : "=r"(a) : "l"(p));
    return a;
}
__device__ __forceinline__ void cp16(uint32_t dst, const void* src) {
    asm volatile("cp.async.cg.shared.global [%0], [%1], 16;" :: "r"(dst), "l"(src));
}
#define CP_COMMIT() asm volatile("cp.async.commit_group;" ::: "memory")
#define CP_WAIT(n)  asm volatile("cp.async.wait_group %0;" :: "n"(n) : "memory")

__device__ __forceinline__ void ldsm_x4(uint32_t& r0, uint32_t& r1, uint32_t& r2,
                                        uint32_t& r3, uint32_t addr) {
    asm volatile("ldmatrix.sync.aligned.m8n8.x4.shared.b16 {%0,%1,%2,%3}, [%4];"
                 : "=r"(r0), "=r"(r1), "=r"(r2), "=r"(r3) : "r"(addr));
}
__device__ __forceinline__ void ldsm_x4_t(uint32_t& r0, uint32_t& r1, uint32_t& r2,
                                          uint32_t& r3, uint32_t addr) {
    asm volatile("ldmatrix.sync.aligned.m8n8.x4.trans.shared.b16 {%0,%1,%2,%3}, [%4];"
                 : "=r"(r0), "=r"(r1), "=r"(r2), "=r"(r3) : "r"(addr));
}
__device__ __forceinline__ void mma16816(float* d, uint32_t a0, uint32_t a1,
                                         uint32_t a2, uint32_t a3,
                                         uint32_t b0, uint32_t b1) {
    asm volatile("mma.sync.aligned.m16n8k16.row.col.f32.f16.f16.f32 "
                 "{%0,%1,%2,%3}, {%4,%5,%6,%7}, {%8,%9}, {%0,%1,%2,%3};"
                 : "+f"(d[0]), "+f"(d[1]), "+f"(d[2]), "+f"(d[3])
                 : "r"(a0), "r"(a1), "r"(a2), "r"(a3), "r"(b0), "r"(b1));
}
__device__ __forceinline__ void f2h_range(const float* __restrict__ in,
                                          __half* __restrict__ out,
                                          int n4, int start, int stride) {
    for (int i = start; i < n4; i += stride) {
        float4 v = ((const float4*)in)[i];
        __half2 p0 = __floats2half2_rn(v.x, v.y);
        __half2 p1 = __floats2half2_rn(v.z, v.w);
        uint2 u;
        u.x = *(uint32_t*)&p0;
        u.y = *(uint32_t*)&p1;
        ((uint2*)out)[i] = u;
    }
}

// ================= upfront float -> half: x and C_w only ====================
__global__ void __launch_bounds__(256)
f2h_qkv_kernel(const float* __restrict__ i0, __half* __restrict__ o0, int n0,
               const float* __restrict__ i1, __half* __restrict__ o1, int n1)
{
    const int start  = blockIdx.x * 256 + threadIdx.x;
    const int stride = gridDim.x * 256;
    f2h_range(i0, o0, n0, start, stride);
    f2h_range(i1, o1, n1, start, stride);
}

// ============ FP16 mma.sync GEMM, 128x128x64, 3-stage, ldmatrix =============
// gridDim.z = split-K count; EPI_PART writes raw fp32 partial (no bias/res).
#define ALD 72     // halves; 144B/row
#define BLD 136    // halves; 272B/row
#define GSTAGES 3
#define STAGE_BYTES (128 * 144 + 64 * 272)      // 35840
#define GEMM_SMEM   (GSTAGES * STAGE_BYTES)     // 107520

enum { EPI_BIAS = 0, EPI_BIAS_GELU = 2, EPI_PART = 3 };

template <int EPI, bool OUTH>
__global__ void __launch_bounds__(256, 2)
gemm_fp16(const __half* __restrict__ A, const __half* __restrict__ B,
          const float* __restrict__ bias,
          void* __restrict__ Cout, int M, int N, int K)
{
    extern __shared__ char smg[];
    const uint32_t sbase = smem_u32(smg);

    const int tid  = threadIdx.x;
    const int lane = tid & 31;
    const int bm   = blockIdx.y;
    const int bn   = blockIdx.x;
    const int warp = tid >> 5;
    const int wm   = warp & 3;
    const int wn   = warp >> 2;

    const int kLen = K / gridDim.z;
    const int kOff = blockIdx.z * kLen;

    float d[2][8][4];
    #pragma unroll
    for (int i = 0; i < 2; ++i)
        #pragma unroll
        for (int j = 0; j < 8; ++j)
            #pragma unroll
            for (int e = 0; e < 4; ++e)
                d[i][j][e] = 0.0f;

    const __half* Aptr = A + (size_t)(bm * 128) * K + kOff;
    const __half* Bptr = B + (size_t)kOff * N + bn * 128;
    const int nT = kLen >> 6;

    auto load_stage = [&](int s, int kt) {
        uint32_t sa = sbase + s * STAGE_BYTES;
        uint32_t sb = sa + 128 * 144;
        #pragma unroll
        for (int i = 0; i < 4; ++i) {
            int idx = tid + i * 256;
            int r = idx >> 3, c = idx & 7;
            cp16(sa + r * 144 + c * 16, Aptr + (size_t)r * K + kt * 64 + c * 8);
        }
        #pragma unroll
        for (int i = 0; i < 4; ++i) {
            int idx = tid + i * 256;
            int r = idx >> 4, c = idx & 15;
            cp16(sb + r * 272 + c * 16, Bptr + (size_t)(kt * 64 + r) * N + c * 8);
        }
    };

    uint32_t aoff[2];
    #pragma unroll
    for (int i = 0; i < 2; ++i)
        aoff[i] = (uint32_t)((wm * 32 + i * 16 + (lane & 15)) * 144 + (lane >> 4) * 16);
    uint32_t boff[4];
    #pragma unroll
    for (int j2 = 0; j2 < 4; ++j2)
        boff[j2] = (uint32_t)((lane & 15) * 272 + (wn * 64 + j2 * 16) * 2 + (lane >> 4) * 16);

    load_stage(0, 0); CP_COMMIT();
    load_stage(1, 1); CP_COMMIT();

    for (int kt = 0; kt < nT; ++kt) {
        if (kt + 1 < nT) { CP_WAIT(1); } else { CP_WAIT(0); }
        __syncthreads();

        if (kt + 2 < nT) { load_stage((kt + 2) % GSTAGES, kt + 2); CP_COMMIT(); }

        const uint32_t sa = sbase + (kt % GSTAGES) * STAGE_BYTES;
        const uint32_t sb = sa + 128 * 144;
        #pragma unroll
        for (int ks = 0; ks < 4; ++ks) {
            uint32_t a[2][4];
            uint32_t b[4][4];
            #pragma unroll
            for (int i = 0; i < 2; ++i)
                ldsm_x4(a[i][0], a[i][1], a[i][2], a[i][3], sa + aoff[i] + ks * 32);
            #pragma unroll
            for (int j2 = 0; j2 < 4; ++j2)
                ldsm_x4_t(b[j2][0], b[j2][1], b[j2][2], b[j2][3],
                          sb + boff[j2] + ks * 4352);
            #pragma unroll
            for (int i = 0; i < 2; ++i)
                #pragma unroll
                for (int j2 = 0; j2 < 4; ++j2) {
                    mma16816(d[i][j2 * 2 + 0], a[i][0], a[i][1], a[i][2], a[i][3],
                             b[j2][0], b[j2][1]);
                    mma16816(d[i][j2 * 2 + 1], a[i][0], a[i][1], a[i][2], a[i][3],
                             b[j2][2], b[j2][3]);
                }
        }
    }
    __syncthreads();

    float* Cs = (float*)smg;  // 128x128 fp32 staging
    {
        const int r0 = (lane >> 2);
        const int c0 = (lane & 3) * 2;
        #pragma unroll
        for (int i = 0; i < 2; ++i) {
            int rbase = wm * 32 + i * 16 + r0;
            #pragma unroll
            for (int j = 0; j < 8; ++j) {
                int cbase = wn * 64 + j * 8 + c0;
                *(float2*)&Cs[rbase * 128 + cbase]       = make_float2(d[i][j][0], d[i][j][1]);
                *(float2*)&Cs[(rbase + 8) * 128 + cbase] = make_float2(d[i][j][2], d[i][j][3]);
            }
        }
    }
    __syncthreads();

    // split-K partial: Cout advanced by z * M * N (fp32 partial buffers)
    float* Pout = (float*)Cout + (EPI == EPI_PART ? (size_t)blockIdx.z * M * N : 0);

    #pragma unroll
    for (int it = 0; it < 16; ++it) {
        int f4 = tid + it * 256;
        int r = f4 >> 5, c4 = f4 & 31;
        float4 v = ((float4*)Cs)[f4];
        int gn = bn * 128 + c4 * 4;
        size_t goff = (size_t)(bm * 128 + r) * N + gn;
        if (EPI == EPI_PART) {
            *(float4*)(Pout + goff) = v;
            continue;
        }
        float4 bv = *(const float4*)(bias + gn);
        v.x += bv.x; v.y += bv.y; v.z += bv.z; v.w += bv.w;
        if (EPI == EPI_BIAS_GELU) {
            v.x = gelu_f(v.x); v.y = gelu_f(v.y);
            v.z = gelu_f(v.z); v.w = gelu_f(v.w);
        }
        if (OUTH) {
            __half2 p0 = __floats2half2_rn(v.x, v.y);
            __half2 p1 = __floats2half2_rn(v.z, v.w);
            uint2 u;
            u.x = *(uint32_t*)&p0;
            u.y = *(uint32_t*)&p1;
            *(uint2*)((__half*)Cout + goff) = u;
        } else {
            *(float4*)((float*)Cout + goff) = v;
        }
    }
}

// ====== causal flash attention (BQ=BK=64) + fused weight f2h workers ========
#define QLDH 136
#define SLDF 68
#define PLDH 136
#define OFF_Q   0
#define OFF_K   17408
#define OFF_V   (OFF_K + 2 * 17408)
#define OFF_S   (OFF_V + 2 * 17408)
#define OFF_RP  (OFF_S + 17408)
#define OFF_M   (OFF_RP + 1024)
#define OFF_L   (OFF_M + 256)
#define OFF_A   (OFF_L + 256)
#define ATT_SMEM (OFF_A + 256)                // 106240 B

__global__ void __launch_bounds__(256, 2)
attn_kernel(const __half* __restrict__ c, __half* __restrict__ out,
            const float* __restrict__ lw,  __half* __restrict__ lh,
            const float* __restrict__ f1w, __half* __restrict__ f1h,
            const float* __restrict__ f2w, __half* __restrict__ f2h)
{
    // ---- f2h worker blocks (low blockIdx.x -> scheduled in wave 1) ----
    if (blockIdx.x < F2H_XBLKS) {
        const int w = blockIdx.x * HEADS + blockIdx.y;           // 0..127
        const int start  = w * 256 + threadIdx.x;
        const int stride = F2H_XBLKS * HEADS * 256;              // 32768
        f2h_range(lw,  lh,  DMODEL * DMODEL / 4, start, stride);
        f2h_range(f1w, f1h, DMODEL * INNER / 4,  start, stride);
        f2h_range(f2w, f2h, INNER * DMODEL / 4,  start, stride);
        return;
    }

    const int h  = blockIdx.y;
    const int qt = (gridDim.x - 1) - blockIdx.x;   // heavy tiles first

    extern __shared__ char smg[];
    const uint32_t sbase = smem_u32(smg);
    __half* Qs    = (__half*)(smg + OFF_Q);
    float*  S     = (float*)(smg + OFF_S);
    __half* P     = (__half*)(smg + OFF_S);     // aliased: same rows, 272B stride
    float* rowpat = (float*)(smg + OFF_RP);
    float* mrow   = (float*)(smg + OFF_M);
    float* lrow   = (float*)(smg + OFF_L);
    float* arow   = (float*)(smg + OFF_A);

    const int tid  = threadIdx.x;
    const int warp = tid >> 5;
    const int wm   = warp & 3;
    const int wn   = warp >> 2;

    auto load_kv = [&](int buf, int j) {
        uint32_t kb = sbase + OFF_K + buf * 17408;
        uint32_t vb = sbase + OFF_V + buf * 17408;
        const __half* base = c + (size_t)(j * 64) * (3 * DMODEL) + h * HDIM;
        #pragma unroll
        for (int i = 0; i < 4; ++i) {
            int idx = tid + i * 256;
            int r = idx >> 4, cc = idx & 15;
            const __half* rp = base + (size_t)r * (3 * DMODEL) + cc * 8;
            cp16(kb + r * 272 + cc * 16, rp + DMODEL);
            cp16(vb + r * 272 + cc * 16, rp + 2 * DMODEL);
        }
    };

    load_kv(0, 0); CP_COMMIT();

    #pragma unroll
    for (int i = 0; i < 4; ++i) {
        int idx = tid + i * 256;
        int r = idx >> 4, cc = idx & 15;
        *(uint4*)((char*)Qs + r * 272 + cc * 16) =
            *(const uint4*)(c + (size_t)(qt * 64 + r) * (3 * DMODEL) + h * HDIM + cc * 8);
    }
    rowpat[tid] = (float)(tid >> 4);
    if (tid < 64) { mrow[tid] = -1e30f; lrow[tid] = 0.0f; }
    __syncthreads();

    wmma::fragment<wmma::accumulator, 16, 16, 16, float> rowf;
    wmma::load_matrix_sync(rowf, rowpat, 16, wmma::mem_row_major);
    int rowid[8];
    #pragma unroll
    for (int e = 0; e < 8; ++e) rowid[e] = (int)rowf.x[e];

    wmma::fragment<wmma::accumulator, 16, 16, 16, float> of[4];
    #pragma unroll
    for (int j = 0; j < 4; ++j) wmma::fill_fragment(of[j], 0.0f);

    const float scale = 0.022097086912079608f;  // 1/sqrt(2048)
    const int srow = tid >> 2, sq = tid & 3;

    for (int j = 0; j <= qt; ++j) {
        if (j < qt) { load_kv((j + 1) & 1, j + 1); CP_COMMIT(); CP_WAIT(1); }
        else        { CP_WAIT(0); }
        __syncthreads();

        const __half* Ks = (const __half*)(smg + OFF_K + (j & 1) * 17408);
        const __half* Vs = (const __half*)(smg + OFF_V + (j & 1) * 17408);

        // S = Q @ K^T : each warp 16x32
        {
            wmma::fragment<wmma::accumulator, 16, 16, 16, float> sf[2];
            wmma::fill_fragment(sf[0], 0.0f);
            wmma::fill_fragment(sf[1], 0.0f);
            #pragma unroll
            for (int ks = 0; ks < 8; ++ks) {
                wmma::fragment<wmma::matrix_a, 16, 16, 16, __half, wmma::row_major> af;
                wmma::load_matrix_sync(af, Qs + (wm * 16) * QLDH + ks * 16, QLDH);
                #pragma unroll
                for (int jj = 0; jj < 2; ++jj) {
                    wmma::fragment<wmma::matrix_b, 16, 16, 16, __half, wmma::col_major> bf;
                    wmma::load_matrix_sync(bf, Ks + (wn * 32 + jj * 16) * QLDH + ks * 16, QLDH);
                    wmma::mma_sync(sf[jj], af, bf, sf[jj]);
                }
            }
            #pragma unroll
            for (int jj = 0; jj < 2; ++jj)
                wmma::store_matrix_sync(S + (wm * 16) * SLDF + wn * 32 + jj * 16,
                                        sf[jj], SLDF, wmma::mem_row_major);
        }
        __syncthreads();

        // online softmax: 4 threads/row; P writes after the converged shuffle
        {
            const bool diag = (j == qt);
            float m_old = mrow[srow];
            float mx = m_old;
            float sv[16];
            #pragma unroll
            for (int k4 = 0; k4 < 4; ++k4) {
                float4 v4 = *(float4*)&S[srow * SLDF + sq * 16 + k4 * 4];
                float* vv = &sv[k4 * 4];
                vv[0] = v4.x * scale; vv[1] = v4.y * scale;
                vv[2] = v4.z * scale; vv[3] = v4.w * scale;
                if (diag) {
                    int kcol = sq * 16 + k4 * 4;
                    if (kcol + 0 > srow) vv[0] = -1e30f;
                    if (kcol + 1 > srow) vv[1] = -1e30f;
                    if (kcol + 2 > srow) vv[2] = -1e30f;
                    if (kcol + 3 > srow) vv[3] = -1e30f;
                }
                mx = fmaxf(mx, fmaxf(fmaxf(vv[0], vv[1]), fmaxf(vv[2], vv[3])));
            }
            mx = fmaxf(mx, __shfl_xor_sync(0xffffffffu, mx, 1));
            mx = fmaxf(mx, __shfl_xor_sync(0xffffffffu, mx, 2));
            float sum = 0.0f;
            __align__(16) uint32_t pw[8];
            #pragma unroll
            for (int k2 = 0; k2 < 8; ++k2) {
                float p0 = __expf(sv[k2 * 2 + 0] - mx);
                float p1 = __expf(sv[k2 * 2 + 1] - mx);
                sum += p0 + p1;
                __half2 hp = __floats2half2_rn(p0, p1);
                pw[k2] = *(uint32_t*)&hp;
            }
            *(uint4*)&P[srow * PLDH + sq * 16]     = *(uint4*)&pw[0];
            *(uint4*)&P[srow * PLDH + sq * 16 + 8] = *(uint4*)&pw[4];
            sum += __shfl_xor_sync(0xffffffffu, sum, 1);
            sum += __shfl_xor_sync(0xffffffffu, sum, 2);
            if (sq == 0) {
                float alpha = __expf(m_old - mx);
                mrow[srow] = mx;
                lrow[srow] = lrow[srow] * alpha + sum;
                arow[srow] = alpha;
            }
        }
        __syncthreads();

        #pragma unroll
        for (int f = 0; f < 4; ++f)
            #pragma unroll
            for (int e = 0; e < 8; ++e)
                of[f].x[e] *= arow[wm * 16 + rowid[e]];

        #pragma unroll
        for (int ks = 0; ks < 4; ++ks) {
            wmma::fragment<wmma::matrix_a, 16, 16, 16, __half, wmma::row_major> pa;
            wmma::load_matrix_sync(pa, P + (wm * 16) * PLDH + ks * 16, PLDH);
            #pragma unroll
            for (int jj = 0; jj < 4; ++jj) {
                wmma::fragment<wmma::matrix_b, 16, 16, 16, __half, wmma::row_major> vb;
                wmma::load_matrix_sync(vb, Vs + (ks * 16) * QLDH + wn * 64 + jj * 16, QLDH);
                wmma::mma_sync(of[jj], pa, vb, of[jj]);
            }
        }
        __syncthreads();
    }

    float* Os = (float*)(smg + OFF_K);   // 64 x 132 fp32 staging
    #pragma unroll
    for (int jj = 0; jj < 4; ++jj)
        wmma::store_matrix_sync(Os + (wm * 16) * 132 + wn * 64 + jj * 16,
                                of[jj], 132, wmma::mem_row_major);
    __syncthreads();
    #pragma unroll
    for (int i = 0; i < 8; ++i) {
        int idx = tid + i * 256;
        int r = idx >> 5, c4 = idx & 31;
        float linv = 1.0f / lrow[r];
        float4 v = *(float4*)(Os + r * 132 + c4 * 4);
        __half2 p0 = __floats2half2_rn(v.x * linv, v.y * linv);
        __half2 p1 = __floats2half2_rn(v.z * linv, v.w * linv);
        uint2 u;
        u.x = *(uint32_t*)&p0;
        u.y = *(uint32_t*)&p1;
        *(uint2*)(out + (size_t)(qt * 64 + r) * DMODEL + h * HDIM + c4 * 4) = u;
    }
}

// ====== LayerNorm over (part0 + part1 + resid + bias), optional half copy ===
__global__ void __launch_bounds__(256)
ln_sum_kernel(const float* __restrict__ p0, const float* __restrict__ p1,
              const float* __restrict__ resid, const float* __restrict__ bias,
              const float* __restrict__ g, const float* __restrict__ b,
              float* __restrict__ out, __half* __restrict__ out_h)
{
    const int row = blockIdx.x;
    const int tid = threadIdx.x;
    const size_t base = (size_t)row * DMODEL;
    const float4* a4 = (const float4*)(p0 + base);
    const float4* b4 = (const float4*)(p1 + base);
    const float4* r4 = (const float4*)(resid + base);
    const float4* c4 = (const float4*)bias;

    float4 v0, v1;
    {
        float4 x0 = a4[tid],       y0 = b4[tid],       z0 = r4[tid],       w0 = c4[tid];
        float4 x1 = a4[tid + 256], y1 = b4[tid + 256], z1 = r4[tid + 256], w1 = c4[tid + 256];
        v0.x = x0.x + y0.x + z0.x + w0.x; v0.y = x0.y + y0.y + z0.y + w0.y;
        v0.z = x0.z + y0.z + z0.z + w0.z; v0.w = x0.w + y0.w + z0.w + w0.w;
        v1.x = x1.x + y1.x + z1.x + w1.x; v1.y = x1.y + y1.y + z1.y + w1.y;
        v1.z = x1.z + y1.z + z1.z + w1.z; v1.w = x1.w + y1.w + z1.w + w1.w;
    }

    float s = v0.x + v0.y + v0.z + v0.w + v1.x + v1.y + v1.z + v1.w;
    float q = v0.x * v0.x + v0.y * v0.y + v0.z * v0.z + v0.w * v0.w
            + v1.x * v1.x + v1.y * v1.y + v1.z * v1.z + v1.w * v1.w;

    #pragma unroll
    for (int o = 16; o > 0; o >>= 1) {
        s += __shfl_down_sync(0xffffffffu, s, o);
        q += __shfl_down_sync(0xffffffffu, q, o);
    }
    __shared__ float rs[8], rq[8], fin[2];
    if ((tid & 31) == 0) { rs[tid >> 5] = s; rq[tid >> 5] = q; }
    __syncthreads();
    if (tid == 0) {
        float S = 0.0f, Q = 0.0f;
        #pragma unroll
        for (int i = 0; i < 8; ++i) { S += rs[i]; Q += rq[i]; }
        float mu  = S * (1.0f / DMODEL);
        float var = Q * (1.0f / DMODEL) - mu * mu;
        fin[0] = mu;
        fin[1] = rsqrtf(var + LN_EPS);
    }
    __syncthreads();
    float mu = fin[0], r = fin[1];

    float4 g0 = ((const float4*)g)[tid], g1 = ((const float4*)g)[tid + 256];
    float4 bb0 = ((const float4*)b)[tid], bb1 = ((const float4*)b)[tid + 256];
    float4 o0, o1;
    o0.x = (v0.x - mu) * r * g0.x + bb0.x;
    o0.y = (v0.y - mu) * r * g0.y + bb0.y;
    o0.z = (v0.z - mu) * r * g0.z + bb0.z;
    o0.w = (v0.w - mu) * r * g0.w + bb0.w;
    o1.x = (v1.x - mu) * r * g1.x + bb1.x;
    o1.y = (v1.y - mu) * r * g1.y + bb1.y;
    o1.z = (v1.z - mu) * r * g1.z + bb1.z;
    o1.w = (v1.w - mu) * r * g1.w + bb1.w;
    ((float4*)(out + base))[tid]       = o0;
    ((float4*)(out + base))[tid + 256] = o1;
    if (out_h) {
        __half2 a0 = __floats2half2_rn(o0.x, o0.y);
        __half2 a1 = __floats2half2_rn(o0.z, o0.w);
        __half2 a2 = __floats2half2_rn(o1.x, o1.y);
        __half2 a3 = __floats2half2_rn(o1.z, o1.w);
        uint2 u0, u1;
        u0.x = *(uint32_t*)&a0; u0.y = *(uint32_t*)&a1;
        u1.x = *(uint32_t*)&a2; u1.y = *(uint32_t*)&a3;
        ((uint2*)(out_h + base))[tid]       = u0;
        ((uint2*)(out_h + base))[tid + 256] = u1;
    }
}

// ================= launch ===================================================
extern "C" void kernel_launch(void* const* d_in, const int* in_sizes, int n_in,
                              void* d_out, int out_size)
{
    (void)in_sizes; (void)n_in; (void)out_size;

    const float* x     = (const float*)d_in[0];
    const float* C_w   = (const float*)d_in[1];
    const float* C_b   = (const float*)d_in[2];
    const float* lin_w = (const float*)d_in[3];
    const float* lin_b = (const float*)d_in[4];
    const float* ff1_w = (const float*)d_in[5];
    const float* ff1_b = (const float*)d_in[6];
    const float* ff2_w = (const float*)d_in[7];
    const float* ff2_b = (const float*)d_in[8];
    const float* ln1_g = (const float*)d_in[9];
    const float* ln1_b = (const float*)d_in[10];
    const float* ln2_g = (const float*)d_in[11];
    const float* ln2_b = (const float*)d_in[12];
    float* out = (float*)d_out;

    __half *c, *attn, *h1h, *ff, *xh, *Cwh, *linh, *ff1h, *ff2h;
    float *h1, *part;
    cudaGetSymbolAddress((void**)&c,    g_c);
    cudaGetSymbolAddress((void**)&attn, g_attn);
    cudaGetSymbolAddress((void**)&h1,   g_h1);
    cudaGetSymbolAddress((void**)&h1h,  g_h1h);
    cudaGetSymbolAddress((void**)&ff,   g_ff);
    cudaGetSymbolAddress((void**)&part, g_part);
    cudaGetSymbolAddress((void**)&xh,   g_xh);
    cudaGetSymbolAddress((void**)&Cwh,  g_Cwh);
    cudaGetSymbolAddress((void**)&linh, g_linh);
    cudaGetSymbolAddress((void**)&ff1h, g_ff1h);
    cudaGetSymbolAddress((void**)&ff2h, g_ff2h);

    cudaFuncSetAttribute((const void*)gemm_fp16<EPI_BIAS, true>,       cudaFuncAttributeMaxDynamicSharedMemorySize, GEMM_SMEM);
    cudaFuncSetAttribute((const void*)gemm_fp16<EPI_BIAS_GELU, true>,  cudaFuncAttributeMaxDynamicSharedMemorySize, GEMM_SMEM);
    cudaFuncSetAttribute((const void*)gemm_fp16<EPI_PART, false>,      cudaFuncAttributeMaxDynamicSharedMemorySize, GEMM_SMEM);
    cudaFuncSetAttribute((const void*)attn_kernel,                     cudaFuncAttributeMaxDynamicSharedMemorySize, ATT_SMEM);

    // 0) convert only x and C_w upfront (QKV inputs)
    f2h_qkv_kernel<<<512, 256>>>(
        x,   xh,  SEQ * DMODEL / 4,
        C_w, Cwh, DMODEL * 3 * DMODEL / 4);

    // 1) QKV: c = half(xh @ C_w + C_b)   [2048, 6144]
    gemm_fp16<EPI_BIAS, true><<<dim3(3 * DMODEL / 128, SEQ / 128), 256, GEMM_SMEM>>>(
        xh, Cwh, C_b, c, SEQ, 3 * DMODEL, DMODEL);

    // 2) causal attention -> attn (half) + fused f2h of lin/ff1/ff2 weights
    attn_kernel<<<dim3(SEQ / 64 + F2H_XBLKS, HEADS), 256, ATT_SMEM>>>(
        c, attn, lin_w, linh, ff1_w, ff1h, ff2_w, ff2h);

    // 3) proj split-K x2: part[z] = attn @ lin_w (partial over K/2)
    gemm_fp16<EPI_PART, false><<<dim3(DMODEL / 128, SEQ / 128, 2), 256, GEMM_SMEM>>>(
        attn, linh, nullptr, part, SEQ, DMODEL, DMODEL);

    // 4) h1 = LN1(part0 + part1 + x + lin_b); h1h = half(h1)
    ln_sum_kernel<<<SEQ, 256>>>(part, part + (size_t)SEQ * DMODEL,
                                x, lin_b, ln1_g, ln1_b, h1, h1h);

    // 5) ff = half(gelu(h1h @ ff1_w + ff1_b))   [2048, 8192]
    gemm_fp16<EPI_BIAS_GELU, true><<<dim3(INNER / 128, SEQ / 128), 256, GEMM_SMEM>>>(
        h1h, ff1h, ff1_b, ff, SEQ, INNER, DMODEL);

    // 6) FF2 split-K x2: part[z] = ff @ ff2_w (partial over K/2)
    gemm_fp16<EPI_PART, false><<<dim3(DMODEL / 128, SEQ / 128, 2), 256, GEMM_SMEM>>>(
        ff, ff2h, nullptr, part, SEQ, DMODEL, INNER);

    // 7) out = LN2(part0 + part1 + h1 + ff2_b)
    ln_sum_kernel<<<SEQ, 256>>>(part, part + (size_t)SEQ * DMODEL,
                                h1, ff2_b, ln2_g, ln2_b, out, nullptr);
}

// round 16
// speedup vs baseline: 1.0172x; 1.0172x over previous
#include <cuda_runtime.h>
#include <cuda_fp16.h>
#include <cstdint>
#include <mma.h>
#include <math.h>

using namespace nvcuda;

// ---------------- constants ----------------
#define SEQ      2048
#define DMODEL   2048
#define HEADS    16
#define HDIM     128
#define INNER    8192
#define LN_EPS   1e-5f
#define F2H_XBLKS 8          // extra attention-grid x-slots doing weight f2h

// ---------------- scratch (static device memory; no allocations) ----------
__device__ __half g_c[SEQ * 3 * DMODEL];     // QKV (half)
__device__ __half g_attn[SEQ * DMODEL];      // attention out (half)
__device__ float  g_res1[SEQ * DMODEL];      // x + proj(attn)
__device__ float  g_h1[SEQ * DMODEL];        // LN1 out fp32 (residual)
__device__ __half g_h1h[SEQ * DMODEL];       // LN1 out half (GEMM A)
__device__ __half g_ff[SEQ * INNER];         // gelu(...) half
__device__ float  g_res2[SEQ * DMODEL];
__device__ __half g_xh[SEQ * DMODEL];        // x half
__device__ __half g_Cwh[DMODEL * 3 * DMODEL];
__device__ __half g_linh[DMODEL * DMODEL];
__device__ __half g_ff1h[DMODEL * INNER];
__device__ __half g_ff2h[INNER * DMODEL];

// ---------------- helpers ----------------
__device__ __forceinline__ float gelu_f(float v) {
    return 0.5f * v * (1.0f + erff(v * 0.7071067811865476f));
}
__device__ __forceinline__ uint32_t smem_u32(const void* p) {
    uint32_t a;
    asm("{ .reg .u64 t; cvta.to.shared.u64 t, %1; cvt.u32.u64 %0, t; }"
        : "=r"(a) : "l"(p));
    return a;
}
__device__ __forceinline__ void cp16(uint32_t dst, const void* src) {
    asm volatile("cp.async.cg.shared.global [%0], [%1], 16;" :: "r"(dst), "l"(src));
}
#define CP_COMMIT() asm volatile("cp.async.commit_group;" ::: "memory")
#define CP_WAIT(n)  asm volatile("cp.async.wait_group %0;" :: "n"(n) : "memory")

__device__ __forceinline__ void ldsm_x4(uint32_t& r0, uint32_t& r1, uint32_t& r2,
                                        uint32_t& r3, uint32_t addr) {
    asm volatile("ldmatrix.sync.aligned.m8n8.x4.shared.b16 {%0,%1,%2,%3}, [%4];"
                 : "=r"(r0), "=r"(r1), "=r"(r2), "=r"(r3) : "r"(addr));
}
__device__ __forceinline__ void ldsm_x4_t(uint32_t& r0, uint32_t& r1, uint32_t& r2,
                                          uint32_t& r3, uint32_t addr) {
    asm volatile("ldmatrix.sync.aligned.m8n8.x4.trans.shared.b16 {%0,%1,%2,%3}, [%4];"
                 : "=r"(r0), "=r"(r1), "=r"(r2), "=r"(r3) : "r"(addr));
}
__device__ __forceinline__ void mma16816(float* d, uint32_t a0, uint32_t a1,
                                         uint32_t a2, uint32_t a3,
                                         uint32_t b0, uint32_t b1) {
    asm volatile("mma.sync.aligned.m16n8k16.row.col.f32.f16.f16.f32 "
                 "{%0,%1,%2,%3}, {%4,%5,%6,%7}, {%8,%9}, {%0,%1,%2,%3};"
                 : "+f"(d[0]), "+f"(d[1]), "+f"(d[2]), "+f"(d[3])
                 : "r"(a0), "r"(a1), "r"(a2), "r"(a3), "r"(b0), "r"(b1));
}
__device__ __forceinline__ void f2h_range(const float* __restrict__ in,
                                          __half* __restrict__ out,
                                          int n4, int start, int stride) {
    for (int i = start; i < n4; i += stride) {
        float4 v = ((const float4*)in)[i];
        __half2 p0 = __floats2half2_rn(v.x, v.y);
        __half2 p1 = __floats2half2_rn(v.z, v.w);
        uint2 u;
        u.x = *(uint32_t*)&p0;
        u.y = *(uint32_t*)&p1;
        ((uint2*)out)[i] = u;
    }
}

// ================= upfront float -> half: x and C_w only ====================
__global__ void __launch_bounds__(256)
f2h_qkv_kernel(const float* __restrict__ i0, __half* __restrict__ o0, int n0,
               const float* __restrict__ i1, __half* __restrict__ o1, int n1)
{
    const int start  = blockIdx.x * 256 + threadIdx.x;
    const int stride = gridDim.x * 256;
    f2h_range(i0, o0, n0, start, stride);
    f2h_range(i1, o1, n1, start, stride);
}

// ============ FP16 mma.sync GEMM, 128x128x64, 3-stage, ldmatrix =============
// Direct register->global epilogue (no smem staging, no epilogue barriers).
#define ALD 72     // halves; 144B/row
#define BLD 136    // halves; 272B/row
#define GSTAGES 3
#define STAGE_BYTES (128 * 144 + 64 * 272)      // 35840
#define GEMM_SMEM   (GSTAGES * STAGE_BYTES)     // 107520

enum { EPI_BIAS = 0, EPI_BIAS_RES = 1, EPI_BIAS_GELU = 2 };

template <int EPI, bool OUTH>
__global__ void __launch_bounds__(256, 2)
gemm_fp16(const __half* __restrict__ A, const __half* __restrict__ B,
          const float* __restrict__ bias, const float* __restrict__ res,
          void* __restrict__ Cout, int M, int N, int K)
{
    extern __shared__ char smg[];
    const uint32_t sbase = smem_u32(smg);

    const int tid  = threadIdx.x;
    const int lane = tid & 31;
    const int bm   = blockIdx.y;
    const int bn   = blockIdx.x;
    const int warp = tid >> 5;
    const int wm   = warp & 3;
    const int wn   = warp >> 2;

    float d[2][8][4];
    #pragma unroll
    for (int i = 0; i < 2; ++i)
        #pragma unroll
        for (int j = 0; j < 8; ++j)
            #pragma unroll
            for (int e = 0; e < 4; ++e)
                d[i][j][e] = 0.0f;

    const __half* Aptr = A + (size_t)(bm * 128) * K;
    const __half* Bptr = B + (size_t)bn * 128;
    const int nT = K >> 6;

    auto load_stage = [&](int s, int kt) {
        uint32_t sa = sbase + s * STAGE_BYTES;
        uint32_t sb = sa + 128 * 144;
        #pragma unroll
        for (int i = 0; i < 4; ++i) {
            int idx = tid + i * 256;
            int r = idx >> 3, c = idx & 7;
            cp16(sa + r * 144 + c * 16, Aptr + (size_t)r * K + kt * 64 + c * 8);
        }
        #pragma unroll
        for (int i = 0; i < 4; ++i) {
            int idx = tid + i * 256;
            int r = idx >> 4, c = idx & 15;
            cp16(sb + r * 272 + c * 16, Bptr + (size_t)(kt * 64 + r) * N + c * 8);
        }
    };

    uint32_t aoff[2];
    #pragma unroll
    for (int i = 0; i < 2; ++i)
        aoff[i] = (uint32_t)((wm * 32 + i * 16 + (lane & 15)) * 144 + (lane >> 4) * 16);
    uint32_t boff[4];
    #pragma unroll
    for (int j2 = 0; j2 < 4; ++j2)
        boff[j2] = (uint32_t)((lane & 15) * 272 + (wn * 64 + j2 * 16) * 2 + (lane >> 4) * 16);

    load_stage(0, 0); CP_COMMIT();
    load_stage(1, 1); CP_COMMIT();

    for (int kt = 0; kt < nT; ++kt) {
        if (kt + 1 < nT) { CP_WAIT(1); } else { CP_WAIT(0); }
        __syncthreads();

        if (kt + 2 < nT) { load_stage((kt + 2) % GSTAGES, kt + 2); CP_COMMIT(); }

        const uint32_t sa = sbase + (kt % GSTAGES) * STAGE_BYTES;
        const uint32_t sb = sa + 128 * 144;
        #pragma unroll
        for (int ks = 0; ks < 4; ++ks) {
            uint32_t a[2][4];
            uint32_t b[4][4];
            #pragma unroll
            for (int i = 0; i < 2; ++i)
                ldsm_x4(a[i][0], a[i][1], a[i][2], a[i][3], sa + aoff[i] + ks * 32);
            #pragma unroll
            for (int j2 = 0; j2 < 4; ++j2)
                ldsm_x4_t(b[j2][0], b[j2][1], b[j2][2], b[j2][3],
                          sb + boff[j2] + ks * 4352);
            #pragma unroll
            for (int i = 0; i < 2; ++i)
                #pragma unroll
                for (int j2 = 0; j2 < 4; ++j2) {
                    mma16816(d[i][j2 * 2 + 0], a[i][0], a[i][1], a[i][2], a[i][3],
                             b[j2][0], b[j2][1]);
                    mma16816(d[i][j2 * 2 + 1], a[i][0], a[i][1], a[i][2], a[i][3],
                             b[j2][2], b[j2][3]);
                }
        }
    }

    // direct register->global epilogue (accum layout: row=lane/4 (+8), col=(lane&3)*2)
    {
        const int r0 = lane >> 2;
        const int c0 = (lane & 3) * 2;
        #pragma unroll
        for (int j = 0; j < 8; ++j) {
            const int gc = bn * 128 + wn * 64 + j * 8 + c0;
            const float2 bv = *(const float2*)(bias + gc);
            #pragma unroll
            for (int i = 0; i < 2; ++i) {
                #pragma unroll
                for (int hh = 0; hh < 2; ++hh) {
                    const int gr = bm * 128 + wm * 32 + i * 16 + hh * 8 + r0;
                    const size_t off = (size_t)gr * N + gc;
                    float vx = d[i][j][hh * 2 + 0] + bv.x;
                    float vy = d[i][j][hh * 2 + 1] + bv.y;
                    if (EPI == EPI_BIAS_RES) {
                        float2 rv = *(const float2*)(res + off);
                        vx += rv.x; vy += rv.y;
                    }
                    if (EPI == EPI_BIAS_GELU) {
                        vx = gelu_f(vx); vy = gelu_f(vy);
                    }
                    if (OUTH) {
                        __half2 hp = __floats2half2_rn(vx, vy);
                        *(uint32_t*)((__half*)Cout + off) = *(uint32_t*)&hp;
                    } else {
                        *(float2*)((float*)Cout + off) = make_float2(vx, vy);
                    }
                }
            }
        }
    }
}

// ====== causal flash attention (BQ=BK=64) + fused weight f2h workers ========
#define QLDH 136
#define SLDF 68
#define PLDH 136
#define OFF_Q   0
#define OFF_K   17408
#define OFF_V   (OFF_K + 2 * 17408)
#define OFF_S   (OFF_V + 2 * 17408)
#define OFF_RP  (OFF_S + 17408)
#define OFF_M   (OFF_RP + 1024)
#define OFF_L   (OFF_M + 256)
#define OFF_A   (OFF_L + 256)
#define ATT_SMEM (OFF_A + 256)                // 106240 B

__global__ void __launch_bounds__(256, 2)
attn_kernel(const __half* __restrict__ c, __half* __restrict__ out,
            const float* __restrict__ lw,  __half* __restrict__ lh,
            const float* __restrict__ f1w, __half* __restrict__ f1h,
            const float* __restrict__ f2w, __half* __restrict__ f2h)
{
    // ---- f2h worker blocks (low blockIdx.x -> scheduled in wave 1) ----
    if (blockIdx.x < F2H_XBLKS) {
        const int w = blockIdx.x * HEADS + blockIdx.y;           // 0..127
        const int start  = w * 256 + threadIdx.x;
        const int stride = F2H_XBLKS * HEADS * 256;              // 32768
        f2h_range(lw,  lh,  DMODEL * DMODEL / 4, start, stride);
        f2h_range(f1w, f1h, DMODEL * INNER / 4,  start, stride);
        f2h_range(f2w, f2h, INNER * DMODEL / 4,  start, stride);
        return;
    }

    const int h  = blockIdx.y;
    const int qt = (gridDim.x - 1) - blockIdx.x;   // heavy tiles first

    extern __shared__ char smg[];
    const uint32_t sbase = smem_u32(smg);
    __half* Qs    = (__half*)(smg + OFF_Q);
    float*  S     = (float*)(smg + OFF_S);
    __half* P     = (__half*)(smg + OFF_S);     // aliased: same rows, 272B stride
    float* rowpat = (float*)(smg + OFF_RP);
    float* mrow   = (float*)(smg + OFF_M);
    float* lrow   = (float*)(smg + OFF_L);
    float* arow   = (float*)(smg + OFF_A);

    const int tid  = threadIdx.x;
    const int warp = tid >> 5;
    const int wm   = warp & 3;
    const int wn   = warp >> 2;

    auto load_kv = [&](int buf, int j) {
        uint32_t kb = sbase + OFF_K + buf * 17408;
        uint32_t vb = sbase + OFF_V + buf * 17408;
        const __half* base = c + (size_t)(j * 64) * (3 * DMODEL) + h * HDIM;
        #pragma unroll
        for (int i = 0; i < 4; ++i) {
            int idx = tid + i * 256;
            int r = idx >> 4, cc = idx & 15;
            const __half* rp = base + (size_t)r * (3 * DMODEL) + cc * 8;
            cp16(kb + r * 272 + cc * 16, rp + DMODEL);
            cp16(vb + r * 272 + cc * 16, rp + 2 * DMODEL);
        }
    };

    load_kv(0, 0); CP_COMMIT();

    #pragma unroll
    for (int i = 0; i < 4; ++i) {
        int idx = tid + i * 256;
        int r = idx >> 4, cc = idx & 15;
        *(uint4*)((char*)Qs + r * 272 + cc * 16) =
            *(const uint4*)(c + (size_t)(qt * 64 + r) * (3 * DMODEL) + h * HDIM + cc * 8);
    }
    rowpat[tid] = (float)(tid >> 4);
    if (tid < 64) { mrow[tid] = -1e30f; lrow[tid] = 0.0f; }
    __syncthreads();

    wmma::fragment<wmma::accumulator, 16, 16, 16, float> rowf;
    wmma::load_matrix_sync(rowf, rowpat, 16, wmma::mem_row_major);
    int rowid[8];
    #pragma unroll
    for (int e = 0; e < 8; ++e) rowid[e] = (int)rowf.x[e];

    wmma::fragment<wmma::accumulator, 16, 16, 16, float> of[4];
    #pragma unroll
    for (int j = 0; j < 4; ++j) wmma::fill_fragment(of[j], 0.0f);

    const float scale = 0.022097086912079608f;  // 1/sqrt(2048)
    const int srow = tid >> 2, sq = tid & 3;

    for (int j = 0; j <= qt; ++j) {
        if (j < qt) { load_kv((j + 1) & 1, j + 1); CP_COMMIT(); CP_WAIT(1); }
        else        { CP_WAIT(0); }
        __syncthreads();

        const __half* Ks = (const __half*)(smg + OFF_K + (j & 1) * 17408);
        const __half* Vs = (const __half*)(smg + OFF_V + (j & 1) * 17408);

        // S = Q @ K^T : each warp 16x32
        {
            wmma::fragment<wmma::accumulator, 16, 16, 16, float> sf[2];
            wmma::fill_fragment(sf[0], 0.0f);
            wmma::fill_fragment(sf[1], 0.0f);
            #pragma unroll
            for (int ks = 0; ks < 8; ++ks) {
                wmma::fragment<wmma::matrix_a, 16, 16, 16, __half, wmma::row_major> af;
                wmma::load_matrix_sync(af, Qs + (wm * 16) * QLDH + ks * 16, QLDH);
                #pragma unroll
                for (int jj = 0; jj < 2; ++jj) {
                    wmma::fragment<wmma::matrix_b, 16, 16, 16, __half, wmma::col_major> bf;
                    wmma::load_matrix_sync(bf, Ks + (wn * 32 + jj * 16) * QLDH + ks * 16, QLDH);
                    wmma::mma_sync(sf[jj], af, bf, sf[jj]);
                }
            }
            #pragma unroll
            for (int jj = 0; jj < 2; ++jj)
                wmma::store_matrix_sync(S + (wm * 16) * SLDF + wn * 32 + jj * 16,
                                        sf[jj], SLDF, wmma::mem_row_major);
        }
        __syncthreads();

        // online softmax: 4 threads/row; P writes after the converged shuffle
        {
            const bool diag = (j == qt);
            float m_old = mrow[srow];
            float mx = m_old;
            float sv[16];
            #pragma unroll
            for (int k4 = 0; k4 < 4; ++k4) {
                float4 v4 = *(float4*)&S[srow * SLDF + sq * 16 + k4 * 4];
                float* vv = &sv[k4 * 4];
                vv[0] = v4.x * scale; vv[1] = v4.y * scale;
                vv[2] = v4.z * scale; vv[3] = v4.w * scale;
                if (diag) {
                    int kcol = sq * 16 + k4 * 4;
                    if (kcol + 0 > srow) vv[0] = -1e30f;
                    if (kcol + 1 > srow) vv[1] = -1e30f;
                    if (kcol + 2 > srow) vv[2] = -1e30f;
                    if (kcol + 3 > srow) vv[3] = -1e30f;
                }
                mx = fmaxf(mx, fmaxf(fmaxf(vv[0], vv[1]), fmaxf(vv[2], vv[3])));
            }
            mx = fmaxf(mx, __shfl_xor_sync(0xffffffffu, mx, 1));
            mx = fmaxf(mx, __shfl_xor_sync(0xffffffffu, mx, 2));
            float sum = 0.0f;
            __align__(16) uint32_t pw[8];
            #pragma unroll
            for (int k2 = 0; k2 < 8; ++k2) {
                float p0 = __expf(sv[k2 * 2 + 0] - mx);
                float p1 = __expf(sv[k2 * 2 + 1] - mx);
                sum += p0 + p1;
                __half2 hp = __floats2half2_rn(p0, p1);
                pw[k2] = *(uint32_t*)&hp;
            }
            *(uint4*)&P[srow * PLDH + sq * 16]     = *(uint4*)&pw[0];
            *(uint4*)&P[srow * PLDH + sq * 16 + 8] = *(uint4*)&pw[4];
            sum += __shfl_xor_sync(0xffffffffu, sum, 1);
            sum += __shfl_xor_sync(0xffffffffu, sum, 2);
            if (sq == 0) {
                float alpha = __expf(m_old - mx);
                mrow[srow] = mx;
                lrow[srow] = lrow[srow] * alpha + sum;
                arow[srow] = alpha;
            }
        }
        __syncthreads();

        #pragma unroll
        for (int f = 0; f < 4; ++f)
            #pragma unroll
            for (int e = 0; e < 8; ++e)
                of[f].x[e] *= arow[wm * 16 + rowid[e]];

        #pragma unroll
        for (int ks = 0; ks < 4; ++ks) {
            wmma::fragment<wmma::matrix_a, 16, 16, 16, __half, wmma::row_major> pa;
            wmma::load_matrix_sync(pa, P + (wm * 16) * PLDH + ks * 16, PLDH);
            #pragma unroll
            for (int jj = 0; jj < 4; ++jj) {
                wmma::fragment<wmma::matrix_b, 16, 16, 16, __half, wmma::row_major> vb;
                wmma::load_matrix_sync(vb, Vs + (ks * 16) * QLDH + wn * 64 + jj * 16, QLDH);
                wmma::mma_sync(of[jj], pa, vb, of[jj]);
            }
        }
        __syncthreads();
    }

    float* Os = (float*)(smg + OFF_K);   // 64 x 132 fp32 staging
    #pragma unroll
    for (int jj = 0; jj < 4; ++jj)
        wmma::store_matrix_sync(Os + (wm * 16) * 132 + wn * 64 + jj * 16,
                                of[jj], 132, wmma::mem_row_major);
    __syncthreads();
    #pragma unroll
    for (int i = 0; i < 8; ++i) {
        int idx = tid + i * 256;
        int r = idx >> 5, c4 = idx & 31;
        float linv = 1.0f / lrow[r];
        float4 v = *(float4*)(Os + r * 132 + c4 * 4);
        __half2 p0 = __floats2half2_rn(v.x * linv, v.y * linv);
        __half2 p1 = __floats2half2_rn(v.z * linv, v.w * linv);
        uint2 u;
        u.x = *(uint32_t*)&p0;
        u.y = *(uint32_t*)&p1;
        *(uint2*)(out + (size_t)(qt * 64 + r) * DMODEL + h * HDIM + c4 * 4) = u;
    }
}

// ================= LayerNorm: one block per row, optional half copy =========
__global__ void __launch_bounds__(256)
ln_kernel(const float* __restrict__ in, const float* __restrict__ g,
          const float* __restrict__ b, float* __restrict__ out,
          __half* __restrict__ out_h)
{
    const int row = blockIdx.x;
    const int tid = threadIdx.x;
    const float4* x4 = (const float4*)(in + (size_t)row * DMODEL);

    float4 v0 = x4[tid];
    float4 v1 = x4[tid + 256];
    float s = v0.x + v0.y + v0.z + v0.w + v1.x + v1.y + v1.z + v1.w;
    float q = v0.x * v0.x + v0.y * v0.y + v0.z * v0.z + v0.w * v0.w
            + v1.x * v1.x + v1.y * v1.y + v1.z * v1.z + v1.w * v1.w;

    #pragma unroll
    for (int o = 16; o > 0; o >>= 1) {
        s += __shfl_down_sync(0xffffffffu, s, o);
        q += __shfl_down_sync(0xffffffffu, q, o);
    }
    __shared__ float rs[8], rq[8], fin[2];
    if ((tid & 31) == 0) { rs[tid >> 5] = s; rq[tid >> 5] = q; }
    __syncthreads();
    if (tid == 0) {
        float S = 0.0f, Q = 0.0f;
        #pragma unroll
        for (int i = 0; i < 8; ++i) { S += rs[i]; Q += rq[i]; }
        float mu  = S * (1.0f / DMODEL);
        float var = Q * (1.0f / DMODEL) - mu * mu;
        fin[0] = mu;
        fin[1] = rsqrtf(var + LN_EPS);
    }
    __syncthreads();
    float mu = fin[0], r = fin[1];

    float4 g0 = ((const float4*)g)[tid], g1 = ((const float4*)g)[tid + 256];
    float4 b0 = ((const float4*)b)[tid], b1 = ((const float4*)b)[tid + 256];
    float4 o0, o1;
    o0.x = (v0.x - mu) * r * g0.x + b0.x;
    o0.y = (v0.y - mu) * r * g0.y + b0.y;
    o0.z = (v0.z - mu) * r * g0.z + b0.z;
    o0.w = (v0.w - mu) * r * g0.w + b0.w;
    o1.x = (v1.x - mu) * r * g1.x + b1.x;
    o1.y = (v1.y - mu) * r * g1.y + b1.y;
    o1.z = (v1.z - mu) * r * g1.z + b1.z;
    o1.w = (v1.w - mu) * r * g1.w + b1.w;
    ((float4*)(out + (size_t)row * DMODEL))[tid]       = o0;
    ((float4*)(out + (size_t)row * DMODEL))[tid + 256] = o1;
    if (out_h) {
        __half2 a0 = __floats2half2_rn(o0.x, o0.y);
        __half2 a1 = __floats2half2_rn(o0.z, o0.w);
        __half2 a2 = __floats2half2_rn(o1.x, o1.y);
        __half2 a3 = __floats2half2_rn(o1.z, o1.w);
        uint2 u0, u1;
        u0.x = *(uint32_t*)&a0; u0.y = *(uint32_t*)&a1;
        u1.x = *(uint32_t*)&a2; u1.y = *(uint32_t*)&a3;
        ((uint2*)(out_h + (size_t)row * DMODEL))[tid]       = u0;
        ((uint2*)(out_h + (size_t)row * DMODEL))[tid + 256] = u1;
    }
}

// ================= launch ===================================================
extern "C" void kernel_launch(void* const* d_in, const int* in_sizes, int n_in,
                              void* d_out, int out_size)
{
    (void)in_sizes; (void)n_in; (void)out_size;

    const float* x     = (const float*)d_in[0];
    const float* C_w   = (const float*)d_in[1];
    const float* C_b   = (const float*)d_in[2];
    const float* lin_w = (const float*)d_in[3];
    const float* lin_b = (const float*)d_in[4];
    const float* ff1_w = (const float*)d_in[5];
    const float* ff1_b = (const float*)d_in[6];
    const float* ff2_w = (const float*)d_in[7];
    const float* ff2_b = (const float*)d_in[8];
    const float* ln1_g = (const float*)d_in[9];
    const float* ln1_b = (const float*)d_in[10];
    const float* ln2_g = (const float*)d_in[11];
    const float* ln2_b = (const float*)d_in[12];
    float* out = (float*)d_out;

    __half *c, *attn, *h1h, *ff, *xh, *Cwh, *linh, *ff1h, *ff2h;
    float *res1, *h1, *res2;
    cudaGetSymbolAddress((void**)&c,    g_c);
    cudaGetSymbolAddress((void**)&attn, g_attn);
    cudaGetSymbolAddress((void**)&res1, g_res1);
    cudaGetSymbolAddress((void**)&h1,   g_h1);
    cudaGetSymbolAddress((void**)&h1h,  g_h1h);
    cudaGetSymbolAddress((void**)&ff,   g_ff);
    cudaGetSymbolAddress((void**)&res2, g_res2);
    cudaGetSymbolAddress((void**)&xh,   g_xh);
    cudaGetSymbolAddress((void**)&Cwh,  g_Cwh);
    cudaGetSymbolAddress((void**)&linh, g_linh);
    cudaGetSymbolAddress((void**)&ff1h, g_ff1h);
    cudaGetSymbolAddress((void**)&ff2h, g_ff2h);

    cudaFuncSetAttribute((const void*)gemm_fp16<EPI_BIAS, true>,       cudaFuncAttributeMaxDynamicSharedMemorySize, GEMM_SMEM);
    cudaFuncSetAttribute((const void*)gemm_fp16<EPI_BIAS_RES, false>,  cudaFuncAttributeMaxDynamicSharedMemorySize, GEMM_SMEM);
    cudaFuncSetAttribute((const void*)gemm_fp16<EPI_BIAS_GELU, true>,  cudaFuncAttributeMaxDynamicSharedMemorySize, GEMM_SMEM);
    cudaFuncSetAttribute((const void*)attn_kernel,                     cudaFuncAttributeMaxDynamicSharedMemorySize, ATT_SMEM);

    // 0) convert only x and C_w upfront (QKV inputs)
    f2h_qkv_kernel<<<512, 256>>>(
        x,   xh,  SEQ * DMODEL / 4,
        C_w, Cwh, DMODEL * 3 * DMODEL / 4);

    // 1) QKV: c = half(xh @ C_w + C_b)   [2048, 6144]
    gemm_fp16<EPI_BIAS, true><<<dim3(3 * DMODEL / 128, SEQ / 128), 256, GEMM_SMEM>>>(
        xh, Cwh, C_b, nullptr, c, SEQ, 3 * DMODEL, DMODEL);

    // 2) causal attention -> attn (half) + fused f2h of lin/ff1/ff2 weights
    attn_kernel<<<dim3(SEQ / 64 + F2H_XBLKS, HEADS), 256, ATT_SMEM>>>(
        c, attn, lin_w, linh, ff1_w, ff1h, ff2_w, ff2h);

    // 3) res1 = x + attn @ lin_w + lin_b  (fp32)
    gemm_fp16<EPI_BIAS_RES, false><<<dim3(DMODEL / 128, SEQ / 128), 256, GEMM_SMEM>>>(
        attn, linh, lin_b, x, res1, SEQ, DMODEL, DMODEL);

    // 4) h1 = LN1(res1); h1h = half(h1)
    ln_kernel<<<SEQ, 256>>>(res1, ln1_g, ln1_b, h1, h1h);

    // 5) ff = half(gelu(h1h @ ff1_w + ff1_b))   [2048, 8192]
    gemm_fp16<EPI_BIAS_GELU, true><<<dim3(INNER / 128, SEQ / 128), 256, GEMM_SMEM>>>(
        h1h, ff1h, ff1_b, nullptr, ff, SEQ, INNER, DMODEL);

    // 6) res2 = h1 + ff @ ff2_w + ff2_b  (fp32)
    gemm_fp16<EPI_BIAS_RES, false><<<dim3(DMODEL / 128, SEQ / 128), 256, GEMM_SMEM>>>(
        ff, ff2h, ff2_b, h1, res2, SEQ, DMODEL, INNER);

    // 7) out = LN2(res2)
    ln_kernel<<<SEQ, 256>>>(res2, ln2_g, ln2_b, out, nullptr);
}

// round 17
// speedup vs baseline: 1.0216x; 1.0043x over previous
#include <cuda_runtime.h>
#include <cuda_fp16.h>
#include <cstdint>
#include <mma.h>
#include <math.h>

using namespace nvcuda;

// ---------------- constants ----------------
#define SEQ      2048
#define DMODEL   2048
#define HEADS    16
#define HDIM     128
#define INNER    8192
#define LN_EPS   1e-5f
#define F2H_XBLKS 8          // extra attention-grid x-slots doing weight f2h

// ---------------- scratch (static device memory; no allocations) ----------
__device__ __half g_c[SEQ * 3 * DMODEL];     // QKV (half)
__device__ __half g_attn[SEQ * DMODEL];      // attention out (half)
__device__ float  g_res1[SEQ * DMODEL];      // x + proj(attn)
__device__ float  g_h1[SEQ * DMODEL];        // LN1 out fp32 (residual)
__device__ __half g_h1h[SEQ * DMODEL];       // LN1 out half (GEMM A)
__device__ __half g_ff[SEQ * INNER];         // gelu(...) half
__device__ float  g_res2[SEQ * DMODEL];
__device__ __half g_xh[SEQ * DMODEL];        // x half
__device__ __half g_Cwh[DMODEL * 3 * DMODEL];
__device__ __half g_linh[DMODEL * DMODEL];
__device__ __half g_ff1h[DMODEL * INNER];
__device__ __half g_ff2h[INNER * DMODEL];

// ---------------- helpers ----------------
__device__ __forceinline__ float gelu_f(float v) {
    return 0.5f * v * (1.0f + erff(v * 0.7071067811865476f));
}
__device__ __forceinline__ uint32_t smem_u32(const void* p) {
    uint32_t a;
    asm("{ .reg .u64 t; cvta.to.shared.u64 t, %1; cvt.u32.u64 %0, t; }"
        : "=r"(a) : "l"(p));
    return a;
}
__device__ __forceinline__ void cp16(uint32_t dst, const void* src) {
    asm volatile("cp.async.cg.shared.global [%0], [%1], 16;" :: "r"(dst), "l"(src));
}
#define CP_COMMIT() asm volatile("cp.async.commit_group;" ::: "memory")
#define CP_WAIT(n)  asm volatile("cp.async.wait_group %0;" :: "n"(n) : "memory")

__device__ __forceinline__ void ldsm_x4(uint32_t& r0, uint32_t& r1, uint32_t& r2,
                                        uint32_t& r3, uint32_t addr) {
    asm volatile("ldmatrix.sync.aligned.m8n8.x4.shared.b16 {%0,%1,%2,%3}, [%4];"
                 : "=r"(r0), "=r"(r1), "=r"(r2), "=r"(r3) : "r"(addr));
}
__device__ __forceinline__ void ldsm_x4_t(uint32_t& r0, uint32_t& r1, uint32_t& r2,
                                          uint32_t& r3, uint32_t addr) {
    asm volatile("ldmatrix.sync.aligned.m8n8.x4.trans.shared.b16 {%0,%1,%2,%3}, [%4];"
                 : "=r"(r0), "=r"(r1), "=r"(r2), "=r"(r3) : "r"(addr));
}
__device__ __forceinline__ void mma16816(float* d, uint32_t a0, uint32_t a1,
                                         uint32_t a2, uint32_t a3,
                                         uint32_t b0, uint32_t b1) {
    asm volatile("mma.sync.aligned.m16n8k16.row.col.f32.f16.f16.f32 "
                 "{%0,%1,%2,%3}, {%4,%5,%6,%7}, {%8,%9}, {%0,%1,%2,%3};"
                 : "+f"(d[0]), "+f"(d[1]), "+f"(d[2]), "+f"(d[3])
                 : "r"(a0), "r"(a1), "r"(a2), "r"(a3), "r"(b0), "r"(b1));
}
__device__ __forceinline__ void f2h_range(const float* __restrict__ in,
                                          __half* __restrict__ out,
                                          int n4, int start, int stride) {
    for (int i = start; i < n4; i += stride) {
        float4 v = ((const float4*)in)[i];
        __half2 p0 = __floats2half2_rn(v.x, v.y);
        __half2 p1 = __floats2half2_rn(v.z, v.w);
        uint2 u;
        u.x = *(uint32_t*)&p0;
        u.y = *(uint32_t*)&p1;
        ((uint2*)out)[i] = u;
    }
}

// ================= upfront float -> half: x and C_w only ====================
__global__ void __launch_bounds__(256)
f2h_qkv_kernel(const float* __restrict__ i0, __half* __restrict__ o0, int n0,
               const float* __restrict__ i1, __half* __restrict__ o1, int n1)
{
    const int start  = blockIdx.x * 256 + threadIdx.x;
    const int stride = gridDim.x * 256;
    f2h_range(i0, o0, n0, start, stride);
    f2h_range(i1, o1, n1, start, stride);
}

// ============ FP16 mma.sync GEMM, 128x128x64, 3-stage, ldmatrix =============
// Warp tile 32x64 via m16n8k16: 2(m) x 8(n) accum tiles, 6 ldmatrix.x4 per k16.
#define ALD 72     // halves; 144B/row
#define BLD 136    // halves; 272B/row
#define GSTAGES 3
#define STAGE_BYTES (128 * 144 + 64 * 272)      // 35840
#define GEMM_SMEM   (GSTAGES * STAGE_BYTES)     // 107520

enum { EPI_BIAS = 0, EPI_BIAS_RES = 1, EPI_BIAS_GELU = 2 };

template <int EPI, bool OUTH>
__global__ void __launch_bounds__(256, 2)
gemm_fp16(const __half* __restrict__ A, const __half* __restrict__ B,
          const float* __restrict__ bias, const float* __restrict__ res,
          void* __restrict__ Cout, int M, int N, int K)
{
    extern __shared__ char smg[];
    const uint32_t sbase = smem_u32(smg);

    const int tid  = threadIdx.x;
    const int lane = tid & 31;
    const int bm   = blockIdx.y;
    const int bn   = blockIdx.x;
    const int warp = tid >> 5;
    const int wm   = warp & 3;
    const int wn   = warp >> 2;

    float d[2][8][4];
    #pragma unroll
    for (int i = 0; i < 2; ++i)
        #pragma unroll
        for (int j = 0; j < 8; ++j)
            #pragma unroll
            for (int e = 0; e < 4; ++e)
                d[i][j][e] = 0.0f;

    const __half* Aptr = A + (size_t)(bm * 128) * K;
    const __half* Bptr = B + (size_t)bn * 128;
    const int nT = K >> 6;

    auto load_stage = [&](int s, int kt) {
        uint32_t sa = sbase + s * STAGE_BYTES;
        uint32_t sb = sa + 128 * 144;
        #pragma unroll
        for (int i = 0; i < 4; ++i) {
            int idx = tid + i * 256;
            int r = idx >> 3, c = idx & 7;
            cp16(sa + r * 144 + c * 16, Aptr + (size_t)r * K + kt * 64 + c * 8);
        }
        #pragma unroll
        for (int i = 0; i < 4; ++i) {
            int idx = tid + i * 256;
            int r = idx >> 4, c = idx & 15;
            cp16(sb + r * 272 + c * 16, Bptr + (size_t)(kt * 64 + r) * N + c * 8);
        }
    };

    uint32_t aoff[2];
    #pragma unroll
    for (int i = 0; i < 2; ++i)
        aoff[i] = (uint32_t)((wm * 32 + i * 16 + (lane & 15)) * 144 + (lane >> 4) * 16);
    uint32_t boff[4];
    #pragma unroll
    for (int j2 = 0; j2 < 4; ++j2)
        boff[j2] = (uint32_t)((lane & 15) * 272 + (wn * 64 + j2 * 16) * 2 + (lane >> 4) * 16);

    load_stage(0, 0); CP_COMMIT();
    load_stage(1, 1); CP_COMMIT();

    for (int kt = 0; kt < nT; ++kt) {
        if (kt + 1 < nT) { CP_WAIT(1); } else { CP_WAIT(0); }
        __syncthreads();   // stage kt visible; all prior MMAs retired

        if (kt + 2 < nT) { load_stage((kt + 2) % GSTAGES, kt + 2); CP_COMMIT(); }

        const uint32_t sa = sbase + (kt % GSTAGES) * STAGE_BYTES;
        const uint32_t sb = sa + 128 * 144;
        #pragma unroll
        for (int ks = 0; ks < 4; ++ks) {
            uint32_t a[2][4];
            uint32_t b[4][4];
            #pragma unroll
            for (int i = 0; i < 2; ++i)
                ldsm_x4(a[i][0], a[i][1], a[i][2], a[i][3], sa + aoff[i] + ks * 32);
            #pragma unroll
            for (int j2 = 0; j2 < 4; ++j2)
                ldsm_x4_t(b[j2][0], b[j2][1], b[j2][2], b[j2][3],
                          sb + boff[j2] + ks * 4352);
            #pragma unroll
            for (int i = 0; i < 2; ++i)
                #pragma unroll
                for (int j2 = 0; j2 < 4; ++j2) {
                    mma16816(d[i][j2 * 2 + 0], a[i][0], a[i][1], a[i][2], a[i][3],
                             b[j2][0], b[j2][1]);
                    mma16816(d[i][j2 * 2 + 1], a[i][0], a[i][1], a[i][2], a[i][3],
                             b[j2][2], b[j2][3]);
                }
        }
    }
    __syncthreads();

    // store accumulators to smem staging (mma layout: row=lane/4 (+8), col=(lane%4)*2)
    float* Cs = (float*)smg;  // 128x128 fp32
    {
        const int r0 = (lane >> 2);
        const int c0 = (lane & 3) * 2;
        #pragma unroll
        for (int i = 0; i < 2; ++i) {
            int rbase = wm * 32 + i * 16 + r0;
            #pragma unroll
            for (int j = 0; j < 8; ++j) {
                int cbase = wn * 64 + j * 8 + c0;
                *(float2*)&Cs[rbase * 128 + cbase]       = make_float2(d[i][j][0], d[i][j][1]);
                *(float2*)&Cs[(rbase + 8) * 128 + cbase] = make_float2(d[i][j][2], d[i][j][3]);
            }
        }
    }
    __syncthreads();

    #pragma unroll
    for (int it = 0; it < 16; ++it) {
        int f4 = tid + it * 256;
        int r = f4 >> 5, c4 = f4 & 31;
        float4 v = ((float4*)Cs)[f4];
        int gn = bn * 128 + c4 * 4;
        float4 bv = *(const float4*)(bias + gn);
        v.x += bv.x; v.y += bv.y; v.z += bv.z; v.w += bv.w;
        size_t goff = (size_t)(bm * 128 + r) * N + gn;
        if (EPI == EPI_BIAS_RES) {
            float4 rv = *(const float4*)(res + goff);
            v.x += rv.x; v.y += rv.y; v.z += rv.z; v.w += rv.w;
        }
        if (EPI == EPI_BIAS_GELU) {
            v.x = gelu_f(v.x); v.y = gelu_f(v.y);
            v.z = gelu_f(v.z); v.w = gelu_f(v.w);
        }
        if (OUTH) {
            __half2 p0 = __floats2half2_rn(v.x, v.y);
            __half2 p1 = __floats2half2_rn(v.z, v.w);
            uint2 u;
            u.x = *(uint32_t*)&p0;
            u.y = *(uint32_t*)&p1;
            *(uint2*)((__half*)Cout + goff) = u;
        } else {
            *(float4*)((float*)Cout + goff) = v;
        }
    }
}

// ====== causal flash attention (BQ=BK=64) + fused weight f2h workers ========
#define QLDH 136
#define SLDF 68
#define PLDH 136
#define OFF_Q   0
#define OFF_K   17408
#define OFF_V   (OFF_K + 2 * 17408)
#define OFF_S   (OFF_V + 2 * 17408)
#define OFF_RP  (OFF_S + 17408)
#define OFF_M   (OFF_RP + 1024)
#define OFF_L   (OFF_M + 256)
#define OFF_A   (OFF_L + 256)
#define ATT_SMEM (OFF_A + 256)                // 106240 B

__global__ void __launch_bounds__(256, 2)
attn_kernel(const __half* __restrict__ c, __half* __restrict__ out,
            const float* __restrict__ lw,  __half* __restrict__ lh,
            const float* __restrict__ f1w, __half* __restrict__ f1h,
            const float* __restrict__ f2w, __half* __restrict__ f2h)
{
    // ---- f2h worker blocks (low blockIdx.x -> scheduled in wave 1) ----
    if (blockIdx.x < F2H_XBLKS) {
        const int w = blockIdx.x * HEADS + blockIdx.y;           // 0..127
        const int start  = w * 256 + threadIdx.x;
        const int stride = F2H_XBLKS * HEADS * 256;              // 32768
        f2h_range(lw,  lh,  DMODEL * DMODEL / 4, start, stride);
        f2h_range(f1w, f1h, DMODEL * INNER / 4,  start, stride);
        f2h_range(f2w, f2h, INNER * DMODEL / 4,  start, stride);
        return;
    }

    const int h  = blockIdx.y;
    const int qt = (gridDim.x - 1) - blockIdx.x;   // heavy tiles first

    extern __shared__ char smg[];
    const uint32_t sbase = smem_u32(smg);
    __half* Qs    = (__half*)(smg + OFF_Q);
    float*  S     = (float*)(smg + OFF_S);
    __half* P     = (__half*)(smg + OFF_S);     // aliased: same rows, 272B stride
    float* rowpat = (float*)(smg + OFF_RP);
    float* mrow   = (float*)(smg + OFF_M);
    float* lrow   = (float*)(smg + OFF_L);
    float* arow   = (float*)(smg + OFF_A);

    const int tid  = threadIdx.x;
    const int warp = tid >> 5;
    const int wm   = warp & 3;
    const int wn   = warp >> 2;

    auto load_kv = [&](int buf, int j) {
        uint32_t kb = sbase + OFF_K + buf * 17408;
        uint32_t vb = sbase + OFF_V + buf * 17408;
        const __half* base = c + (size_t)(j * 64) * (3 * DMODEL) + h * HDIM;
        #pragma unroll
        for (int i = 0; i < 4; ++i) {
            int idx = tid + i * 256;
            int r = idx >> 4, cc = idx & 15;
            const __half* rp = base + (size_t)r * (3 * DMODEL) + cc * 8;
            cp16(kb + r * 272 + cc * 16, rp + DMODEL);
            cp16(vb + r * 272 + cc * 16, rp + 2 * DMODEL);
        }
    };

    load_kv(0, 0); CP_COMMIT();

    #pragma unroll
    for (int i = 0; i < 4; ++i) {
        int idx = tid + i * 256;
        int r = idx >> 4, cc = idx & 15;
        *(uint4*)((char*)Qs + r * 272 + cc * 16) =
            *(const uint4*)(c + (size_t)(qt * 64 + r) * (3 * DMODEL) + h * HDIM + cc * 8);
    }
    rowpat[tid] = (float)(tid >> 4);
    if (tid < 64) { mrow[tid] = -1e30f; lrow[tid] = 0.0f; }
    __syncthreads();

    wmma::fragment<wmma::accumulator, 16, 16, 16, float> rowf;
    wmma::load_matrix_sync(rowf, rowpat, 16, wmma::mem_row_major);
    int rowid[8];
    #pragma unroll
    for (int e = 0; e < 8; ++e) rowid[e] = (int)rowf.x[e];

    wmma::fragment<wmma::accumulator, 16, 16, 16, float> of[4];
    #pragma unroll
    for (int j = 0; j < 4; ++j) wmma::fill_fragment(of[j], 0.0f);

    const float scale = 0.022097086912079608f;  // 1/sqrt(2048)
    const int srow = tid >> 2, sq = tid & 3;

    for (int j = 0; j <= qt; ++j) {
        if (j < qt) { load_kv((j + 1) & 1, j + 1); CP_COMMIT(); CP_WAIT(1); }
        else        { CP_WAIT(0); }
        __syncthreads();

        const __half* Ks = (const __half*)(smg + OFF_K + (j & 1) * 17408);
        const __half* Vs = (const __half*)(smg + OFF_V + (j & 1) * 17408);

        // S = Q @ K^T : each warp 16x32
        {
            wmma::fragment<wmma::accumulator, 16, 16, 16, float> sf[2];
            wmma::fill_fragment(sf[0], 0.0f);
            wmma::fill_fragment(sf[1], 0.0f);
            #pragma unroll
            for (int ks = 0; ks < 8; ++ks) {
                wmma::fragment<wmma::matrix_a, 16, 16, 16, __half, wmma::row_major> af;
                wmma::load_matrix_sync(af, Qs + (wm * 16) * QLDH + ks * 16, QLDH);
                #pragma unroll
                for (int jj = 0; jj < 2; ++jj) {
                    wmma::fragment<wmma::matrix_b, 16, 16, 16, __half, wmma::col_major> bf;
                    wmma::load_matrix_sync(bf, Ks + (wn * 32 + jj * 16) * QLDH + ks * 16, QLDH);
                    wmma::mma_sync(sf[jj], af, bf, sf[jj]);
                }
            }
            #pragma unroll
            for (int jj = 0; jj < 2; ++jj)
                wmma::store_matrix_sync(S + (wm * 16) * SLDF + wn * 32 + jj * 16,
                                        sf[jj], SLDF, wmma::mem_row_major);
        }
        __syncthreads();

        // online softmax: 4 threads/row; P writes after the converged shuffle
        {
            const bool diag = (j == qt);
            float m_old = mrow[srow];
            float mx = m_old;
            float sv[16];
            #pragma unroll
            for (int k4 = 0; k4 < 4; ++k4) {
                float4 v4 = *(float4*)&S[srow * SLDF + sq * 16 + k4 * 4];
                float* vv = &sv[k4 * 4];
                vv[0] = v4.x * scale; vv[1] = v4.y * scale;
                vv[2] = v4.z * scale; vv[3] = v4.w * scale;
                if (diag) {
                    int kcol = sq * 16 + k4 * 4;
                    if (kcol + 0 > srow) vv[0] = -1e30f;
                    if (kcol + 1 > srow) vv[1] = -1e30f;
                    if (kcol + 2 > srow) vv[2] = -1e30f;
                    if (kcol + 3 > srow) vv[3] = -1e30f;
                }
                mx = fmaxf(mx, fmaxf(fmaxf(vv[0], vv[1]), fmaxf(vv[2], vv[3])));
            }
            mx = fmaxf(mx, __shfl_xor_sync(0xffffffffu, mx, 1));
            mx = fmaxf(mx, __shfl_xor_sync(0xffffffffu, mx, 2));
            float sum = 0.0f;
            __align__(16) uint32_t pw[8];
            #pragma unroll
            for (int k2 = 0; k2 < 8; ++k2) {
                float p0 = __expf(sv[k2 * 2 + 0] - mx);
                float p1 = __expf(sv[k2 * 2 + 1] - mx);
                sum += p0 + p1;
                __half2 hp = __floats2half2_rn(p0, p1);
                pw[k2] = *(uint32_t*)&hp;
            }
            *(uint4*)&P[srow * PLDH + sq * 16]     = *(uint4*)&pw[0];
            *(uint4*)&P[srow * PLDH + sq * 16 + 8] = *(uint4*)&pw[4];
            sum += __shfl_xor_sync(0xffffffffu, sum, 1);
            sum += __shfl_xor_sync(0xffffffffu, sum, 2);
            if (sq == 0) {
                float alpha = __expf(m_old - mx);
                mrow[srow] = mx;
                lrow[srow] = lrow[srow] * alpha + sum;
                arow[srow] = alpha;
            }
        }
        __syncthreads();

        #pragma unroll
        for (int f = 0; f < 4; ++f)
            #pragma unroll
            for (int e = 0; e < 8; ++e)
                of[f].x[e] *= arow[wm * 16 + rowid[e]];

        #pragma unroll
        for (int ks = 0; ks < 4; ++ks) {
            wmma::fragment<wmma::matrix_a, 16, 16, 16, __half, wmma::row_major> pa;
            wmma::load_matrix_sync(pa, P + (wm * 16) * PLDH + ks * 16, PLDH);
            #pragma unroll
            for (int jj = 0; jj < 4; ++jj) {
                wmma::fragment<wmma::matrix_b, 16, 16, 16, __half, wmma::row_major> vb;
                wmma::load_matrix_sync(vb, Vs + (ks * 16) * QLDH + wn * 64 + jj * 16, QLDH);
                wmma::mma_sync(of[jj], pa, vb, of[jj]);
            }
        }
        __syncthreads();
    }

    float* Os = (float*)(smg + OFF_K);   // 64 x 132 fp32 staging
    #pragma unroll
    for (int jj = 0; jj < 4; ++jj)
        wmma::store_matrix_sync(Os + (wm * 16) * 132 + wn * 64 + jj * 16,
                                of[jj], 132, wmma::mem_row_major);
    __syncthreads();
    #pragma unroll
    for (int i = 0; i < 8; ++i) {
        int idx = tid + i * 256;
        int r = idx >> 5, c4 = idx & 31;
        float linv = 1.0f / lrow[r];
        float4 v = *(float4*)(Os + r * 132 + c4 * 4);
        __half2 p0 = __floats2half2_rn(v.x * linv, v.y * linv);
        __half2 p1 = __floats2half2_rn(v.z * linv, v.w * linv);
        uint2 u;
        u.x = *(uint32_t*)&p0;
        u.y = *(uint32_t*)&p1;
        *(uint2*)(out + (size_t)(qt * 64 + r) * DMODEL + h * HDIM + c4 * 4) = u;
    }
}

// ================= LayerNorm: one block per row, optional half copy =========
__global__ void __launch_bounds__(256)
ln_kernel(const float* __restrict__ in, const float* __restrict__ g,
          const float* __restrict__ b, float* __restrict__ out,
          __half* __restrict__ out_h)
{
    const int row = blockIdx.x;
    const int tid = threadIdx.x;
    const float4* x4 = (const float4*)(in + (size_t)row * DMODEL);

    float4 v0 = x4[tid];
    float4 v1 = x4[tid + 256];
    float s = v0.x + v0.y + v0.z + v0.w + v1.x + v1.y + v1.z + v1.w;
    float q = v0.x * v0.x + v0.y * v0.y + v0.z * v0.z + v0.w * v0.w
            + v1.x * v1.x + v1.y * v1.y + v1.z * v1.z + v1.w * v1.w;

    #pragma unroll
    for (int o = 16; o > 0; o >>= 1) {
        s += __shfl_down_sync(0xffffffffu, s, o);
        q += __shfl_down_sync(0xffffffffu, q, o);
    }
    __shared__ float rs[8], rq[8], fin[2];
    if ((tid & 31) == 0) { rs[tid >> 5] = s; rq[tid >> 5] = q; }
    __syncthreads();
    if (tid == 0) {
        float S = 0.0f, Q = 0.0f;
        #pragma unroll
        for (int i = 0; i < 8; ++i) { S += rs[i]; Q += rq[i]; }
        float mu  = S * (1.0f / DMODEL);
        float var = Q * (1.0f / DMODEL) - mu * mu;
        fin[0] = mu;
        fin[1] = rsqrtf(var + LN_EPS);
    }
    __syncthreads();
    float mu = fin[0], r = fin[1];

    float4 g0 = ((const float4*)g)[tid], g1 = ((const float4*)g)[tid + 256];
    float4 b0 = ((const float4*)b)[tid], b1 = ((const float4*)b)[tid + 256];
    float4 o0, o1;
    o0.x = (v0.x - mu) * r * g0.x + b0.x;
    o0.y = (v0.y - mu) * r * g0.y + b0.y;
    o0.z = (v0.z - mu) * r * g0.z + b0.z;
    o0.w = (v0.w - mu) * r * g0.w + b0.w;
    o1.x = (v1.x - mu) * r * g1.x + b1.x;
    o1.y = (v1.y - mu) * r * g1.y + b1.y;
    o1.z = (v1.z - mu) * r * g1.z + b1.z;
    o1.w = (v1.w - mu) * r * g1.w + b1.w;
    ((float4*)(out + (size_t)row * DMODEL))[tid]       = o0;
    ((float4*)(out + (size_t)row * DMODEL))[tid + 256] = o1;
    if (out_h) {
        __half2 a0 = __floats2half2_rn(o0.x, o0.y);
        __half2 a1 = __floats2half2_rn(o0.z, o0.w);
        __half2 a2 = __floats2half2_rn(o1.x, o1.y);
        __half2 a3 = __floats2half2_rn(o1.z, o1.w);
        uint2 u0, u1;
        u0.x = *(uint32_t*)&a0; u0.y = *(uint32_t*)&a1;
        u1.x = *(uint32_t*)&a2; u1.y = *(uint32_t*)&a3;
        ((uint2*)(out_h + (size_t)row * DMODEL))[tid]       = u0;
        ((uint2*)(out_h + (size_t)row * DMODEL))[tid + 256] = u1;
    }
}

// ================= launch ===================================================
extern "C" void kernel_launch(void* const* d_in, const int* in_sizes, int n_in,
                              void* d_out, int out_size)
{
    (void)in_sizes; (void)n_in; (void)out_size;

    const float* x     = (const float*)d_in[0];
    const float* C_w   = (const float*)d_in[1];
    const float* C_b   = (const float*)d_in[2];
    const float* lin_w = (const float*)d_in[3];
    const float* lin_b = (const float*)d_in[4];
    const float* ff1_w = (const float*)d_in[5];
    const float* ff1_b = (const float*)d_in[6];
    const float* ff2_w = (const float*)d_in[7];
    const float* ff2_b = (const float*)d_in[8];
    const float* ln1_g = (const float*)d_in[9];
    const float* ln1_b = (const float*)d_in[10];
    const float* ln2_g = (const float*)d_in[11];
    const float* ln2_b = (const float*)d_in[12];
    float* out = (float*)d_out;

    __half *c, *attn, *h1h, *ff, *xh, *Cwh, *linh, *ff1h, *ff2h;
    float *res1, *h1, *res2;
    cudaGetSymbolAddress((void**)&c,    g_c);
    cudaGetSymbolAddress((void**)&attn, g_attn);
    cudaGetSymbolAddress((void**)&res1, g_res1);
    cudaGetSymbolAddress((void**)&h1,   g_h1);
    cudaGetSymbolAddress((void**)&h1h,  g_h1h);
    cudaGetSymbolAddress((void**)&ff,   g_ff);
    cudaGetSymbolAddress((void**)&res2, g_res2);
    cudaGetSymbolAddress((void**)&xh,   g_xh);
    cudaGetSymbolAddress((void**)&Cwh,  g_Cwh);
    cudaGetSymbolAddress((void**)&linh, g_linh);
    cudaGetSymbolAddress((void**)&ff1h, g_ff1h);
    cudaGetSymbolAddress((void**)&ff2h, g_ff2h);

    cudaFuncSetAttribute((const void*)gemm_fp16<EPI_BIAS, true>,       cudaFuncAttributeMaxDynamicSharedMemorySize, GEMM_SMEM);
    cudaFuncSetAttribute((const void*)gemm_fp16<EPI_BIAS_RES, false>,  cudaFuncAttributeMaxDynamicSharedMemorySize, GEMM_SMEM);
    cudaFuncSetAttribute((const void*)gemm_fp16<EPI_BIAS_GELU, true>,  cudaFuncAttributeMaxDynamicSharedMemorySize, GEMM_SMEM);
    cudaFuncSetAttribute((const void*)attn_kernel,                     cudaFuncAttributeMaxDynamicSharedMemorySize, ATT_SMEM);

    // 0) convert only x and C_w upfront (QKV inputs)
    f2h_qkv_kernel<<<512, 256>>>(
        x,   xh,  SEQ * DMODEL / 4,
        C_w, Cwh, DMODEL * 3 * DMODEL / 4);

    // 1) QKV: c = half(xh @ C_w + C_b)   [2048, 6144]
    gemm_fp16<EPI_BIAS, true><<<dim3(3 * DMODEL / 128, SEQ / 128), 256, GEMM_SMEM>>>(
        xh, Cwh, C_b, nullptr, c, SEQ, 3 * DMODEL, DMODEL);

    // 2) causal attention -> attn (half) + fused f2h of lin/ff1/ff2 weights
    attn_kernel<<<dim3(SEQ / 64 + F2H_XBLKS, HEADS), 256, ATT_SMEM>>>(
        c, attn, lin_w, linh, ff1_w, ff1h, ff2_w, ff2h);

    // 3) res1 = x + attn @ lin_w + lin_b  (fp32)
    gemm_fp16<EPI_BIAS_RES, false><<<dim3(DMODEL / 128, SEQ / 128), 256, GEMM_SMEM>>>(
        attn, linh, lin_b, x, res1, SEQ, DMODEL, DMODEL);

    // 4) h1 = LN1(res1); h1h = half(h1)
    ln_kernel<<<SEQ, 256>>>(res1, ln1_g, ln1_b, h1, h1h);

    // 5) ff = half(gelu(h1h @ ff1_w + ff1_b))   [2048, 8192]
    gemm_fp16<EPI_BIAS_GELU, true><<<dim3(INNER / 128, SEQ / 128), 256, GEMM_SMEM>>>(
        h1h, ff1h, ff1_b, nullptr, ff, SEQ, INNER, DMODEL);

    // 6) res2 = h1 + ff @ ff2_w + ff2_b  (fp32)
    gemm_fp16<EPI_BIAS_RES, false><<<dim3(DMODEL / 128, SEQ / 128), 256, GEMM_SMEM>>>(
        ff, ff2h, ff2_b, h1, res2, SEQ, DMODEL, INNER);

    // 7) out = LN2(res2)
    ln_kernel<<<SEQ, 256>>>(res2, ln2_g, ln2_b, out, nullptr);
}